// round 15
// baseline (speedup 1.0000x reference)
#include <cuda_runtime.h>
#include <cuda_fp16.h>
#include <cstdint>
#include <math.h>

// Problem constants
#define BB 2
#define TT 2048
#define EMB 1024
#define HEADS 16
#define HS 64
#define NROWS (BB*TT)          // 4096
#define GK 1024                // K for both GEMMs

// Q pre-scale: hs^-0.5 * log2(e)  (softmax runs in exp2 domain)
#define QSCALE 0.180336880f

// ---------------------------------------------------------------------------
// Scratch (__device__ globals). 1-term fp16. x and w_proj are converted
// on-the-fly inside the GEMM loaders; only w_qkv is pre-converted.
// ---------------------------------------------------------------------------
__device__ __half g_qhi[(size_t)BB*HEADS*TT*HS];   // [bh][t][d], pre-scaled QSCALE
__device__ __half g_khi[(size_t)BB*HEADS*TT*HS];
__device__ __half g_vhi[(size_t)BB*HEADS*TT*HS];

__device__ __half g_ahi[(size_t)NROWS*GK];         // attention out (proj input)
__device__ __half g_wqhi[(size_t)GK*3*EMB];        // [1024][3072] K-major rows

// ---------------------------------------------------------------------------
// PTX helpers (portable sm_80+ subset: ldmatrix / mma.sync / cp.async)
// ---------------------------------------------------------------------------
__device__ __forceinline__ uint32_t smem_u32(const void* p) {
    uint32_t a;
    asm("{ .reg .u64 t; cvta.to.shared.u64 t, %1; cvt.u32.u64 %0, t; }" : "=r"(a) : "l"(p));
    return a;
}
__device__ __forceinline__ void cp16(uint32_t dst, const void* src) {
    asm volatile("cp.async.cg.shared.global [%0], [%1], 16;" :: "r"(dst), "l"(src));
}
__device__ __forceinline__ void cp_commit() {
    asm volatile("cp.async.commit_group;" ::: "memory");
}
template<int N>
__device__ __forceinline__ void cp_wait() {
    asm volatile("cp.async.wait_group %0;" :: "n"(N) : "memory");
}
__device__ __forceinline__ void ldsm4(uint32_t* r, uint32_t a) {
    asm volatile("ldmatrix.sync.aligned.m8n8.x4.shared.b16 {%0,%1,%2,%3}, [%4];"
        : "=r"(r[0]), "=r"(r[1]), "=r"(r[2]), "=r"(r[3]) : "r"(a));
}
// trans x4: [k][n]-stored rows -> col-major B fragments (validated on V path)
__device__ __forceinline__ void ldsm4t(uint32_t* r, uint32_t a) {
    asm volatile("ldmatrix.sync.aligned.m8n8.x4.trans.shared.b16 {%0,%1,%2,%3}, [%4];"
        : "=r"(r[0]), "=r"(r[1]), "=r"(r[2]), "=r"(r[3]) : "r"(a));
}
__device__ __forceinline__ void mma16816(float* d, const uint32_t* a, const uint32_t* b) {
    asm volatile("mma.sync.aligned.m16n8k16.row.col.f32.f16.f16.f32 "
        "{%0,%1,%2,%3}, {%4,%5,%6,%7}, {%8,%9}, {%0,%1,%2,%3};"
        : "+f"(d[0]), "+f"(d[1]), "+f"(d[2]), "+f"(d[3])
        : "r"(a[0]), "r"(a[1]), "r"(a[2]), "r"(a[3]), "r"(b[0]), "r"(b[1]));
}
__device__ __forceinline__ uint32_t packh2(float a, float b) {
    __half2 h = __floats2half2_rn(a, b);
    return *(uint32_t*)&h;
}
// guaranteed single-MUFU exp2
__device__ __forceinline__ float ex2(float x) {
    float y;
    asm("ex2.approx.ftz.f32 %0, %1;" : "=f"(y) : "f"(x));
    return y;
}
// convert 8 fp32 -> 8 fp16 packed as uint4 (same rounding as prep's)
__device__ __forceinline__ uint4 cvt8(const float* p) {
    float4 a = *(const float4*)p, b = *(const float4*)(p + 4);
    uint4 o;
    o.x = packh2(a.x, a.y); o.y = packh2(a.z, a.w);
    o.z = packh2(b.x, b.y); o.w = packh2(b.z, b.w);
    return o;
}

// ---------------------------------------------------------------------------
// Prep: fp32 -> fp16 convert of w_qkv ONLY (x, w_proj converted in-GEMM).
//  wq: 786,432 float4 / 256 threads = 3072 blocks
// ---------------------------------------------------------------------------
__global__ void prep_wq(const float4* __restrict__ wq, __half2* __restrict__ wqo)
{
    int i = blockIdx.x * 256 + threadIdx.x;
    float4 v = wq[i];
    uint4 o;
    o.x = packh2(v.x, v.y); o.y = packh2(v.z, v.w);
    i = i; // (two half2 pairs per float4)
    ((uint2*)wqo)[i] = make_uint2(o.x, o.y);
}

// ---------------------------------------------------------------------------
// HMMA GEMM: C[M,N] = A[M,1024] * W[1024,N], fp16, fp32 accumulate.
// A [M][K] K-major (144B rows, ldsm4); W [K][N] native (272B rows, ldsm4t).
// 128x128 tile, BK=64 (16 iters), 8 warps (2x4), double buffer, 2 CTA/SM.
// CVTA: A source is fp32, converted in-loader.  CVTW: same for W.
// EPI=0: scatter into g_qhi (xQSCALE), g_khi, g_vhi    EPI=1: +bias -> Cout
// ---------------------------------------------------------------------------
#define BKG 64
#define MATA (128 * 144)              // 18432 B A tile
#define MATW (64 * 272)               // 17408 B W tile
#define STAGEB (MATA + MATW)          // 35840
#define GEMM_SMEM (2 * STAGEB)        // 71680

template<int EPI, int CVTA, int CVTW>
__global__ __launch_bounds__(256, 2)
void mma_gemm(const void* __restrict__ Asrc, const void* __restrict__ Wsrc,
              const float* __restrict__ bias, float* __restrict__ Cout, int Nw)
{
    cudaGridDependencySynchronize();

    extern __shared__ char smc[];
    const uint32_t sb = smem_u32(smc);

    const int tid = threadIdx.x;
    const int wid = tid >> 5, lane = tid & 31;
    const int warp_m = wid >> 2;      // 0..1
    const int warp_n = wid & 3;       // 0..3
    const int m0 = blockIdx.y * 128, n0 = blockIdx.x * 128;

    // loader: A 1024 16B-chunks (4/thread), W 1024 (4/thread) per stage.
    auto issue = [&](int kc, int s) {
        char* base = smc + s * STAGEB;
        // W chunks
        #pragma unroll
        for (int i = 0; i < 4; i++) {
            int idx = i * 256 + tid;            // 0..1023
            int r = idx >> 4, c16 = idx & 15;
            if (CVTW) {
                const float* p = (const float*)Wsrc
                    + (size_t)(kc * BKG + r) * Nw + n0 + c16 * 8;
                *(uint4*)(base + MATA + r * 272 + c16 * 16) = cvt8(p);
            } else {
                cp16(sb + s * STAGEB + MATA + r * 272 + c16 * 16,
                     (const __half*)Wsrc + (size_t)(kc * BKG + r) * Nw + n0 + c16 * 8);
            }
        }
        // A chunks
        #pragma unroll
        for (int i = 0; i < 4; i++) {
            int idx = i * 256 + tid;            // 0..1023
            int r = idx >> 3, c8 = idx & 7;
            if (CVTA) {
                const float* p = (const float*)Asrc
                    + (size_t)(m0 + r) * GK + kc * BKG + c8 * 8;
                *(uint4*)(base + r * 144 + c8 * 16) = cvt8(p);
            } else {
                cp16(sb + s * STAGEB + r * 144 + c8 * 16,
                     (const __half*)Asrc + (size_t)(m0 + r) * GK + kc * BKG + c8 * 8);
            }
        }
        cp_commit();
    };

    float acc[4][4][4];
    #pragma unroll
    for (int a = 0; a < 4; a++)
        #pragma unroll
        for (int b = 0; b < 4; b++)
            #pragma unroll
            for (int c = 0; c < 4; c++) acc[a][b][c] = 0.f;

    issue(0, 0);
    const int NIT = GK / BKG;           // 16
    for (int kc = 0; kc < NIT; kc++) {
        const int s = kc & 1;
        if (kc + 1 < NIT) { issue(kc + 1, s ^ 1); cp_wait<1>(); }
        else              { cp_wait<0>(); }
        __syncthreads();

        const uint32_t Ah = sb + s * STAGEB;
        const uint32_t Wh = Ah + MATA;

        #pragma unroll
        for (int ks = 0; ks < 4; ks++) {
            const uint32_t kb = ks * 32 + (lane >> 4) * 16;
            uint32_t ah[4][4];
            #pragma unroll
            for (int mt = 0; mt < 4; mt++) {
                uint32_t ro = Ah + (uint32_t)(warp_m * 64 + mt * 16 + (lane & 15)) * 144 + kb;
                ldsm4(ah[mt], ro);
            }
            #pragma unroll
            for (int ntp = 0; ntp < 2; ntp++) {
                uint32_t ro = Wh + (uint32_t)(ks * 16 + (lane & 15)) * 272
                             + warp_n * 64 + ntp * 32 + (lane >> 4) * 16;
                uint32_t bb[4];
                ldsm4t(bb, ro);
                #pragma unroll
                for (int mt = 0; mt < 4; mt++) {
                    mma16816(acc[mt][2*ntp],     ah[mt], bb);
                    mma16816(acc[mt][2*ntp + 1], ah[mt], bb + 2);
                }
            }
        }
        __syncthreads();
    }

    const int g = lane >> 2, tg = lane & 3;
    #pragma unroll
    for (int mt = 0; mt < 4; mt++) {
        #pragma unroll
        for (int nt = 0; nt < 4; nt++) {
            const int c  = n0 + warp_n * 32 + nt * 8 + tg * 2;
            const int r0 = m0 + warp_m * 64 + mt * 16 + g;
            #pragma unroll
            for (int h = 0; h < 2; h++) {
                const int r = r0 + h * 8;
                float2 v = make_float2(acc[mt][nt][2*h], acc[mt][nt][2*h+1]);
                if (EPI == 0) {
                    const int bb2 = r >> 11, t = r & 2047;
                    const int mat = c >> 10, cc = c & 1023;
                    const int head = cc >> 6, d = cc & 63;
                    size_t o = (((size_t)(bb2 * HEADS + head) * TT + t) * HS + d) >> 1;
                    if (mat == 0) {
                        ((__half2*)g_qhi)[o] = __floats2half2_rn(v.x * QSCALE, v.y * QSCALE);
                    } else if (mat == 1) {
                        ((__half2*)g_khi)[o] = __floats2half2_rn(v.x, v.y);
                    } else {
                        ((__half2*)g_vhi)[o] = __floats2half2_rn(v.x, v.y);
                    }
                } else {
                    float2 bv = *(const float2*)(bias + c);
                    v.x += bv.x; v.y += bv.y;
                    *(float2*)(Cout + (size_t)r * EMB + c) = v;
                }
            }
        }
    }
}

// ---------------------------------------------------------------------------
// Tensor-core flash attention (R11-validated, byte-frozen).
// fp16, exp2-domain softmax (ex2.approx), LPT grid, de-phased warps, PDL.
// ---------------------------------------------------------------------------
#define ATILE_B  (64 * 144)            // 9216 B per 64-row tile
#define ASTAGE_B (2 * ATILE_B)         // Khi, Vhi = 18432
#define ATT_SMEM (4 * ASTAGE_B)        // 73728 (4 buffers; covers Q staging)

__global__ __launch_bounds__(256, 2)
void attn_mma()
{
    cudaGridDependencySynchronize();

    extern __shared__ char sm[];
    const uint32_t sb = smem_u32(sm);
    const int tid = threadIdx.x, wid = tid >> 5, lane = tid & 31;
    const int bh = blockIdx.x;                     // 0..31
    const int qt = gridDim.y - 1 - blockIdx.y;     // heavy tiles first, globally
    const int q0 = qt * 128;
    const int g = lane >> 2, tg = lane & 3;

    // ---- stage Q into smem, then ldmatrix to registers ----
    {
        const __half* Qh = g_qhi + ((size_t)bh * TT + q0) * HS;
        #pragma unroll
        for (int i = 0; i < 4; i++) {
            int idx = i * 256 + tid;               // 0..1023
            int r = idx >> 3, c8 = idx & 7;
            *(uint4*)(sm + r * 144 + c8 * 16) = *(const uint4*)(Qh + r * HS + c8 * 8);
        }
    }
    __syncthreads();
    uint32_t qh[4][4];
    #pragma unroll
    for (int kg = 0; kg < 4; kg++) {
        uint32_t a = sb + (uint32_t)(wid * 16 + (lane & 15)) * 144 + kg * 32 + (lane >> 4) * 16;
        ldsm4(qh[kg], a);
    }
    __syncthreads();

    // ---- K/V pipeline: buffer = tile & 3 ----
    auto issueKV = [&](int kt) {
        const uint32_t dstb = sb + (kt & 3) * ASTAGE_B;
        const size_t rowb = ((size_t)bh * TT + kt * 64) * HS;
        #pragma unroll
        for (int i = 0; i < 4; i++) {
            int idx = i * 256 + tid;               // 0..1023
            int mtx = idx >> 9;                    // 0 Khi 1 Vhi
            int r = (idx >> 3) & 63, c8 = idx & 7;
            const __half* p = (mtx == 0 ? g_khi : g_vhi) + rowb + r * HS + c8 * 8;
            cp16(dstb + mtx * ATILE_B + r * 144 + c8 * 16, p);
        }
        cp_commit();
    };

    float oacc[8][4];
    #pragma unroll
    for (int nt = 0; nt < 8; nt++)
        #pragma unroll
        for (int c = 0; c < 4; c++) oacc[nt][c] = 0.f;
    float mrow[2] = {-1e30f, -1e30f}, lrow[2] = {0.f, 0.f};

    const int dq = (q0 + wid * 16) >> 6;           // warp's diagonal 64-tile
    const int NT = 2 * qt + 2;                     // always even
    const int first = wid & 1;                     // de-phase: odd warps reverse

    issueKV(0); issueKV(1);
    if (NT > 2) { issueKV(2); issueKV(3); }

    for (int j = 0; j < NT / 2; j++) {
        if (2 * j + 3 >= NT) cp_wait<0>(); else cp_wait<2>();
        __syncthreads();

        #pragma unroll
        for (int u = 0; u < 2; u++) {
            const int tt = first ^ u;
            const int kt = 2 * j + tt;
            if (kt > dq) continue;
            const uint32_t base = sb + (kt & 3) * ASTAGE_B;

            // S = Q K^T  (paired ldsm4 for K)   [exp2 domain]
            float sacc[8][4];
            #pragma unroll
            for (int nt = 0; nt < 8; nt++)
                #pragma unroll
                for (int c = 0; c < 4; c++) sacc[nt][c] = 0.f;

            #pragma unroll
            for (int kg = 0; kg < 4; kg++) {
                const uint32_t kbb = kg * 32 + ((lane >> 3) & 1) * 16;
                #pragma unroll
                for (int ntp = 0; ntp < 4; ntp++) {
                    uint32_t ro = base + (uint32_t)(ntp * 16
                                 + (lane >> 4) * 8 + (lane & 7)) * 144 + kbb;
                    uint32_t kb4[4];
                    ldsm4(kb4, ro);
                    mma16816(sacc[2*ntp],     qh[kg], kb4);
                    mma16816(sacc[2*ntp + 1], qh[kg], kb4 + 2);
                }
            }

            // causal mask on the diagonal tile
            if (kt == dq) {
                const int rl = ((q0 + wid * 16) & 63) + g;
                #pragma unroll
                for (int nt = 0; nt < 8; nt++) {
                    int c0 = nt * 8 + tg * 2;
                    if (c0     > rl)     sacc[nt][0] = -1e30f;
                    if (c0 + 1 > rl)     sacc[nt][1] = -1e30f;
                    if (c0     > rl + 8) sacc[nt][2] = -1e30f;
                    if (c0 + 1 > rl + 8) sacc[nt][3] = -1e30f;
                }
            }

            // online softmax in exp2 domain (rows g, g+8; quad reduction)
            #pragma unroll
            for (int r = 0; r < 2; r++) {
                float mx = -1e30f;
                #pragma unroll
                for (int nt = 0; nt < 8; nt++)
                    mx = fmaxf(mx, fmaxf(sacc[nt][2*r], sacc[nt][2*r+1]));
                mx = fmaxf(mx, __shfl_xor_sync(0xffffffffu, mx, 1));
                mx = fmaxf(mx, __shfl_xor_sync(0xffffffffu, mx, 2));
                float mnew = fmaxf(mrow[r], mx);
                float corr = ex2(mrow[r] - mnew);
                float rs = 0.f;
                #pragma unroll
                for (int nt = 0; nt < 8; nt++) {
                    float p0 = ex2(sacc[nt][2*r]   - mnew);
                    float p1 = ex2(sacc[nt][2*r+1] - mnew);
                    sacc[nt][2*r] = p0; sacc[nt][2*r+1] = p1;
                    rs += p0 + p1;
                }
                rs += __shfl_xor_sync(0xffffffffu, rs, 1);
                rs += __shfl_xor_sync(0xffffffffu, rs, 2);
                lrow[r] = lrow[r] * corr + rs;
                mrow[r] = mnew;
                #pragma unroll
                for (int nt = 0; nt < 8; nt++) {
                    oacc[nt][2*r] *= corr; oacc[nt][2*r+1] *= corr;
                }
            }

            // O += P V  (paired ldsm4t for V)
            #pragma unroll
            for (int kg = 0; kg < 4; kg++) {
                uint32_t ph[4];
                #pragma unroll
                for (int q = 0; q < 4; q++) {
                    ph[q] = packh2(sacc[2*kg + (q >> 1)][(q & 1) * 2],
                                   sacc[2*kg + (q >> 1)][(q & 1) * 2 + 1]);
                }
                #pragma unroll
                for (int ntp = 0; ntp < 4; ntp++) {
                    uint32_t ro = base + ATILE_B
                                 + (uint32_t)(kg * 16 + (lane & 15)) * 144
                                 + ntp * 32 + (lane >> 4) * 16;
                    uint32_t vb4[4];
                    ldsm4t(vb4, ro);
                    mma16816(oacc[2*ntp],     ph, vb4);
                    mma16816(oacc[2*ntp + 1], ph, vb4 + 2);
                }
            }
        }
        __syncthreads();
        if (2 * j + 4 < NT) issueKV(2 * j + 4);
        if (2 * j + 5 < NT) issueKV(2 * j + 5);
    }

    // epilogue: write fp16 directly as the proj-GEMM A operand
    const int b = bh >> 4, h = bh & 15;
    #pragma unroll
    for (int r = 0; r < 2; r++) {
        float inv = 1.0f / lrow[r];
        int t = q0 + wid * 16 + g + r * 8;
        size_t rowo = ((size_t)(b * TT + t)) * EMB + h * HS;
        #pragma unroll
        for (int nt = 0; nt < 8; nt++) {
            size_t o = (rowo + nt * 8 + tg * 2) >> 1;
            ((__half2*)g_ahi)[o] =
                __floats2half2_rn(oacc[nt][2*r] * inv, oacc[nt][2*r+1] * inv);
        }
    }
}

// ---------------------------------------------------------------------------
// Host: PDL chain  prep_wq -> gemm0 -> attn -> proj
// ---------------------------------------------------------------------------
template<typename K, typename... Args>
static void launch_pdl(K kern, dim3 grid, dim3 block, size_t smem, Args... args)
{
    cudaLaunchConfig_t cfg = {};
    cfg.gridDim = grid;
    cfg.blockDim = block;
    cfg.dynamicSmemBytes = smem;
    cfg.stream = 0;
    cudaLaunchAttribute attrs[1];
    attrs[0].id = cudaLaunchAttributeProgrammaticStreamSerialization;
    attrs[0].val.programmaticStreamSerializationAllowed = 1;
    cfg.attrs = attrs;
    cfg.numAttrs = 1;
    cudaLaunchKernelEx(&cfg, kern, args...);
}

extern "C" void kernel_launch(void* const* d_in, const int* in_sizes, int n_in,
                              void* d_out, int out_size)
{
    const float* x      = (const float*)d_in[0];
    const float* w_qkv  = (const float*)d_in[1];
    const float* w_proj = (const float*)d_in[2];
    const float* b_proj = (const float*)d_in[3];
    float* out = (float*)d_out;

    cudaFuncSetAttribute(attn_mma, cudaFuncAttributeMaxDynamicSharedMemorySize, ATT_SMEM);
    cudaFuncSetAttribute(mma_gemm<0,1,0>, cudaFuncAttributeMaxDynamicSharedMemorySize, GEMM_SMEM);
    cudaFuncSetAttribute(mma_gemm<1,0,1>, cudaFuncAttributeMaxDynamicSharedMemorySize, GEMM_SMEM);

    __half *ahi, *wqhi;
    cudaGetSymbolAddress((void**)&ahi,  g_ahi);
    cudaGetSymbolAddress((void**)&wqhi, g_wqhi);

    // 1. prep: convert w_qkv only (x and w_proj converted in-GEMM)
    prep_wq<<<3072, 256>>>((const float4*)w_qkv, (__half2*)wqhi);

    // 2. QKV GEMM: A = x fp32 (in-loader convert), W = wqhi fp16
    launch_pdl(mma_gemm<0,1,0>, dim3(3 * EMB / 128, NROWS / 128), dim3(256), GEMM_SMEM,
               (const void*)x, (const void*)wqhi,
               (const float*)nullptr, (float*)nullptr, 3 * EMB);

    // 3. tensor-core causal flash attention (LPT grid, de-phased warps)
    launch_pdl(attn_mma, dim3(BB * HEADS, TT / 128), dim3(256), ATT_SMEM);

    // 4. output projection: A = ahi fp16, W = w_proj fp32 (in-loader convert)
    launch_pdl(mma_gemm<1,0,1>, dim3(EMB / 128, NROWS / 128), dim3(256), GEMM_SMEM,
               (const void*)ahi, (const void*)w_proj,
               b_proj, out, EMB);
}

// round 16
// speedup vs baseline: 1.0889x; 1.0889x over previous
#include <cuda_runtime.h>
#include <cuda_fp16.h>
#include <cstdint>
#include <math.h>

// Problem constants
#define BB 2
#define TT 2048
#define EMB 1024
#define HEADS 16
#define HS 64
#define NROWS (BB*TT)          // 4096
#define GK 1024                // K for both GEMMs

// Q pre-scale: hs^-0.5 * log2(e)  (softmax runs in exp2 domain)
#define QSCALE 0.180336880f

// ---------------------------------------------------------------------------
// Scratch (__device__ globals; allocation-free rule). 1-term fp16 everywhere.
// Weights stay in native [K][N] layout (no transpose) — B frags via ldsm4t.
// ---------------------------------------------------------------------------
__device__ __half g_qhi[(size_t)BB*HEADS*TT*HS];   // [bh][t][d], pre-scaled QSCALE
__device__ __half g_khi[(size_t)BB*HEADS*TT*HS];
__device__ __half g_vhi[(size_t)BB*HEADS*TT*HS];

__device__ __half g_xhi[(size_t)NROWS*GK];
__device__ __half g_ahi[(size_t)NROWS*GK];         // attention out (proj input)
__device__ __half g_wqhi[(size_t)GK*3*EMB];        // [1024][3072] K-major rows
__device__ __half g_wphi[(size_t)GK*EMB];          // [1024][1024] K-major rows

// ---------------------------------------------------------------------------
// PTX helpers (portable sm_80+ subset: ldmatrix / mma.sync / cp.async)
// ---------------------------------------------------------------------------
__device__ __forceinline__ uint32_t smem_u32(const void* p) {
    uint32_t a;
    asm("{ .reg .u64 t; cvta.to.shared.u64 t, %1; cvt.u32.u64 %0, t; }" : "=r"(a) : "l"(p));
    return a;
}
__device__ __forceinline__ void cp16(uint32_t dst, const void* src) {
    asm volatile("cp.async.cg.shared.global [%0], [%1], 16;" :: "r"(dst), "l"(src));
}
__device__ __forceinline__ void cp_commit() {
    asm volatile("cp.async.commit_group;" ::: "memory");
}
template<int N>
__device__ __forceinline__ void cp_wait() {
    asm volatile("cp.async.wait_group %0;" :: "n"(N) : "memory");
}
__device__ __forceinline__ void ldsm4(uint32_t* r, uint32_t a) {
    asm volatile("ldmatrix.sync.aligned.m8n8.x4.shared.b16 {%0,%1,%2,%3}, [%4];"
        : "=r"(r[0]), "=r"(r[1]), "=r"(r[2]), "=r"(r[3]) : "r"(a));
}
// trans x4: [k][n]-stored rows -> col-major B fragments (validated on V path)
__device__ __forceinline__ void ldsm4t(uint32_t* r, uint32_t a) {
    asm volatile("ldmatrix.sync.aligned.m8n8.x4.trans.shared.b16 {%0,%1,%2,%3}, [%4];"
        : "=r"(r[0]), "=r"(r[1]), "=r"(r[2]), "=r"(r[3]) : "r"(a));
}
__device__ __forceinline__ void mma16816(float* d, const uint32_t* a, const uint32_t* b) {
    asm volatile("mma.sync.aligned.m16n8k16.row.col.f32.f16.f16.f32 "
        "{%0,%1,%2,%3}, {%4,%5,%6,%7}, {%8,%9}, {%0,%1,%2,%3};"
        : "+f"(d[0]), "+f"(d[1]), "+f"(d[2]), "+f"(d[3])
        : "r"(a[0]), "r"(a[1]), "r"(a[2]), "r"(a[3]), "r"(b[0]), "r"(b[1]));
}
__device__ __forceinline__ uint32_t packh2(float a, float b) {
    __half2 h = __floats2half2_rn(a, b);
    return *(uint32_t*)&h;
}
// guaranteed single-MUFU exp2 (independent of fast-math flags)
__device__ __forceinline__ float ex2(float x) {
    float y;
    asm("ex2.approx.ftz.f32 %0, %1;" : "=f"(y) : "f"(x));
    return y;
}

// ---------------------------------------------------------------------------
// Prep: pure elementwise fp32 -> fp16 convert of x, w_qkv, w_proj (flat).
// ---------------------------------------------------------------------------
#define NX4  1048576
#define NWQ4 786432

__global__ void prep_all(const float4* __restrict__ x, __half2* __restrict__ xo,
                         const float4* __restrict__ wq, __half2* __restrict__ wqo,
                         const float4* __restrict__ wp, __half2* __restrict__ wpo)
{
    int i = blockIdx.x * 256 + threadIdx.x;
    const float4* src; __half2* dst;
    if (i < NX4)             { src = x;  dst = xo; }
    else if (i < NX4 + NWQ4) { src = wq; dst = wqo; i -= NX4; }
    else                     { src = wp; dst = wpo; i -= NX4 + NWQ4; }
    float4 v = src[i];
    dst[2*i]   = __floats2half2_rn(v.x, v.y);
    dst[2*i+1] = __floats2half2_rn(v.z, v.w);
    cudaTriggerProgrammaticLaunchCompletion();
}

// ---------------------------------------------------------------------------
// HMMA GEMM (R12-validated): C[M,N] = A[M,1024] * W[1024,N], fp16.
// A [M][K] K-major (144B rows, ldsm4); W [K][N] native (272B rows, ldsm4t).
// 128x128 tile, BK=64 (16 iters), 8 warps (2x4), double buffer, 2 CTA/SM.
// PDL: grid-dependency sync before any global reads; early trigger after
// the epilogue's last store.
// ---------------------------------------------------------------------------
#define BKG 64
#define MATA (128 * 144)              // 18432 B A tile
#define MATW (64 * 272)               // 17408 B W tile
#define STAGEB (MATA + MATW)          // 35840
#define GEMM_SMEM (2 * STAGEB)        // 71680

template<int EPI>
__global__ __launch_bounds__(256, 2)
void mma_gemm(const __half* __restrict__ Ahi, const __half* __restrict__ Wm,
              const float* __restrict__ bias, float* __restrict__ Cout, int Nw)
{
    cudaGridDependencySynchronize();

    extern __shared__ char smc[];
    const uint32_t sb = smem_u32(smc);

    const int tid = threadIdx.x;
    const int wid = tid >> 5, lane = tid & 31;
    const int warp_m = wid >> 2;      // 0..1
    const int warp_n = wid & 3;       // 0..3
    const int m0 = blockIdx.y * 128, n0 = blockIdx.x * 128;

    auto issue = [&](int kc, int s) {
        const uint32_t dstb = sb + s * STAGEB;
        #pragma unroll
        for (int i = 0; i < 8; i++) {
            int idx = i * 256 + tid;            // 0..2047
            if (idx < 1024) {                   // A tile: 128 rows x 8 chunks
                int r = idx >> 3, c8 = idx & 7;
                cp16(dstb + r * 144 + c8 * 16,
                     Ahi + (size_t)(m0 + r) * GK + kc * BKG + c8 * 8);
            } else {                            // W tile: 64 k-rows x 16 chunks
                int i2 = idx - 1024;
                int r = i2 >> 4, c16 = i2 & 15;
                cp16(dstb + MATA + r * 272 + c16 * 16,
                     Wm + (size_t)(kc * BKG + r) * Nw + n0 + c16 * 8);
            }
        }
        cp_commit();
    };

    float acc[4][4][4];
    #pragma unroll
    for (int a = 0; a < 4; a++)
        #pragma unroll
        for (int b = 0; b < 4; b++)
            #pragma unroll
            for (int c = 0; c < 4; c++) acc[a][b][c] = 0.f;

    issue(0, 0);
    const int NIT = GK / BKG;           // 16
    for (int kc = 0; kc < NIT; kc++) {
        const int s = kc & 1;
        if (kc + 1 < NIT) { issue(kc + 1, s ^ 1); cp_wait<1>(); }
        else              { cp_wait<0>(); }
        __syncthreads();

        const uint32_t Ah = sb + s * STAGEB;
        const uint32_t Wh = Ah + MATA;

        #pragma unroll
        for (int ks = 0; ks < 4; ks++) {
            const uint32_t kb = ks * 32 + (lane >> 4) * 16;
            uint32_t ah[4][4];
            #pragma unroll
            for (int mt = 0; mt < 4; mt++) {
                uint32_t ro = Ah + (uint32_t)(warp_m * 64 + mt * 16 + (lane & 15)) * 144 + kb;
                ldsm4(ah[mt], ro);
            }
            #pragma unroll
            for (int ntp = 0; ntp < 2; ntp++) {
                uint32_t ro = Wh + (uint32_t)(ks * 16 + (lane & 15)) * 272
                             + warp_n * 64 + ntp * 32 + (lane >> 4) * 16;
                uint32_t bb[4];
                ldsm4t(bb, ro);
                #pragma unroll
                for (int mt = 0; mt < 4; mt++) {
                    mma16816(acc[mt][2*ntp],     ah[mt], bb);
                    mma16816(acc[mt][2*ntp + 1], ah[mt], bb + 2);
                }
            }
        }
        __syncthreads();
    }

    const int g = lane >> 2, tg = lane & 3;
    #pragma unroll
    for (int mt = 0; mt < 4; mt++) {
        #pragma unroll
        for (int nt = 0; nt < 4; nt++) {
            const int c  = n0 + warp_n * 32 + nt * 8 + tg * 2;
            const int r0 = m0 + warp_m * 64 + mt * 16 + g;
            #pragma unroll
            for (int h = 0; h < 2; h++) {
                const int r = r0 + h * 8;
                float2 v = make_float2(acc[mt][nt][2*h], acc[mt][nt][2*h+1]);
                if (EPI == 0) {
                    const int bb2 = r >> 11, t = r & 2047;
                    const int mat = c >> 10, cc = c & 1023;
                    const int head = cc >> 6, d = cc & 63;
                    size_t o = (((size_t)(bb2 * HEADS + head) * TT + t) * HS + d) >> 1;
                    if (mat == 0) {
                        ((__half2*)g_qhi)[o] = __floats2half2_rn(v.x * QSCALE, v.y * QSCALE);
                    } else if (mat == 1) {
                        ((__half2*)g_khi)[o] = __floats2half2_rn(v.x, v.y);
                    } else {
                        ((__half2*)g_vhi)[o] = __floats2half2_rn(v.x, v.y);
                    }
                } else {
                    float2 bv = *(const float2*)(bias + c);
                    v.x += bv.x; v.y += bv.y;
                    *(float2*)(Cout + (size_t)r * EMB + c) = v;
                }
            }
        }
    }
    cudaTriggerProgrammaticLaunchCompletion();
}

// ---------------------------------------------------------------------------
// Tensor-core flash attention (R11-validated structure).
// fp16, exp2-domain softmax (ex2.approx), LPT grid, de-phased warps, PDL.
// ---------------------------------------------------------------------------
#define ATILE_B  (64 * 144)            // 9216 B per 64-row tile
#define ASTAGE_B (2 * ATILE_B)         // Khi, Vhi = 18432
#define ATT_SMEM (4 * ASTAGE_B)        // 73728 (4 buffers; covers Q staging)

__global__ __launch_bounds__(256, 2)
void attn_mma()
{
    cudaGridDependencySynchronize();

    extern __shared__ char sm[];
    const uint32_t sb = smem_u32(sm);
    const int tid = threadIdx.x, wid = tid >> 5, lane = tid & 31;
    const int bh = blockIdx.x;                     // 0..31
    const int qt = gridDim.y - 1 - blockIdx.y;     // heavy tiles first, globally
    const int q0 = qt * 128;
    const int g = lane >> 2, tg = lane & 3;

    // ---- stage Q into smem, then ldmatrix to registers ----
    {
        const __half* Qh = g_qhi + ((size_t)bh * TT + q0) * HS;
        #pragma unroll
        for (int i = 0; i < 4; i++) {
            int idx = i * 256 + tid;               // 0..1023
            int r = idx >> 3, c8 = idx & 7;
            *(uint4*)(sm + r * 144 + c8 * 16) = *(const uint4*)(Qh + r * HS + c8 * 8);
        }
    }
    __syncthreads();
    uint32_t qh[4][4];
    #pragma unroll
    for (int kg = 0; kg < 4; kg++) {
        uint32_t a = sb + (uint32_t)(wid * 16 + (lane & 15)) * 144 + kg * 32 + (lane >> 4) * 16;
        ldsm4(qh[kg], a);
    }
    __syncthreads();

    // ---- K/V pipeline: buffer = tile & 3 ----
    auto issueKV = [&](int kt) {
        const uint32_t dstb = sb + (kt & 3) * ASTAGE_B;
        const size_t rowb = ((size_t)bh * TT + kt * 64) * HS;
        #pragma unroll
        for (int i = 0; i < 4; i++) {
            int idx = i * 256 + tid;               // 0..1023
            int mtx = idx >> 9;                    // 0 Khi 1 Vhi
            int r = (idx >> 3) & 63, c8 = idx & 7;
            const __half* p = (mtx == 0 ? g_khi : g_vhi) + rowb + r * HS + c8 * 8;
            cp16(dstb + mtx * ATILE_B + r * 144 + c8 * 16, p);
        }
        cp_commit();
    };

    float oacc[8][4];
    #pragma unroll
    for (int nt = 0; nt < 8; nt++)
        #pragma unroll
        for (int c = 0; c < 4; c++) oacc[nt][c] = 0.f;
    float mrow[2] = {-1e30f, -1e30f}, lrow[2] = {0.f, 0.f};

    const int dq = (q0 + wid * 16) >> 6;           // warp's diagonal 64-tile
    const int NT = 2 * qt + 2;                     // always even
    const int first = wid & 1;                     // de-phase: odd warps reverse

    issueKV(0); issueKV(1);
    if (NT > 2) { issueKV(2); issueKV(3); }

    for (int j = 0; j < NT / 2; j++) {
        if (2 * j + 3 >= NT) cp_wait<0>(); else cp_wait<2>();
        __syncthreads();

        #pragma unroll
        for (int u = 0; u < 2; u++) {
            const int tt = first ^ u;
            const int kt = 2 * j + tt;
            if (kt > dq) continue;
            const uint32_t base = sb + (kt & 3) * ASTAGE_B;

            // S = Q K^T  (paired ldsm4 for K)   [exp2 domain]
            float sacc[8][4];
            #pragma unroll
            for (int nt = 0; nt < 8; nt++)
                #pragma unroll
                for (int c = 0; c < 4; c++) sacc[nt][c] = 0.f;

            #pragma unroll
            for (int kg = 0; kg < 4; kg++) {
                const uint32_t kbb = kg * 32 + ((lane >> 3) & 1) * 16;
                #pragma unroll
                for (int ntp = 0; ntp < 4; ntp++) {
                    uint32_t ro = base + (uint32_t)(ntp * 16
                                 + (lane >> 4) * 8 + (lane & 7)) * 144 + kbb;
                    uint32_t kb4[4];
                    ldsm4(kb4, ro);
                    mma16816(sacc[2*ntp],     qh[kg], kb4);
                    mma16816(sacc[2*ntp + 1], qh[kg], kb4 + 2);
                }
            }

            // causal mask on the diagonal tile
            if (kt == dq) {
                const int rl = ((q0 + wid * 16) & 63) + g;
                #pragma unroll
                for (int nt = 0; nt < 8; nt++) {
                    int c0 = nt * 8 + tg * 2;
                    if (c0     > rl)     sacc[nt][0] = -1e30f;
                    if (c0 + 1 > rl)     sacc[nt][1] = -1e30f;
                    if (c0     > rl + 8) sacc[nt][2] = -1e30f;
                    if (c0 + 1 > rl + 8) sacc[nt][3] = -1e30f;
                }
            }

            // online softmax in exp2 domain (rows g, g+8; quad reduction)
            #pragma unroll
            for (int r = 0; r < 2; r++) {
                float mx = -1e30f;
                #pragma unroll
                for (int nt = 0; nt < 8; nt++)
                    mx = fmaxf(mx, fmaxf(sacc[nt][2*r], sacc[nt][2*r+1]));
                mx = fmaxf(mx, __shfl_xor_sync(0xffffffffu, mx, 1));
                mx = fmaxf(mx, __shfl_xor_sync(0xffffffffu, mx, 2));
                float mnew = fmaxf(mrow[r], mx);
                float corr = ex2(mrow[r] - mnew);
                float rs = 0.f;
                #pragma unroll
                for (int nt = 0; nt < 8; nt++) {
                    float p0 = ex2(sacc[nt][2*r]   - mnew);
                    float p1 = ex2(sacc[nt][2*r+1] - mnew);
                    sacc[nt][2*r] = p0; sacc[nt][2*r+1] = p1;
                    rs += p0 + p1;
                }
                rs += __shfl_xor_sync(0xffffffffu, rs, 1);
                rs += __shfl_xor_sync(0xffffffffu, rs, 2);
                lrow[r] = lrow[r] * corr + rs;
                mrow[r] = mnew;
                #pragma unroll
                for (int nt = 0; nt < 8; nt++) {
                    oacc[nt][2*r] *= corr; oacc[nt][2*r+1] *= corr;
                }
            }

            // O += P V  (paired ldsm4t for V)
            #pragma unroll
            for (int kg = 0; kg < 4; kg++) {
                uint32_t ph[4];
                #pragma unroll
                for (int q = 0; q < 4; q++) {
                    ph[q] = packh2(sacc[2*kg + (q >> 1)][(q & 1) * 2],
                                   sacc[2*kg + (q >> 1)][(q & 1) * 2 + 1]);
                }
                #pragma unroll
                for (int ntp = 0; ntp < 4; ntp++) {
                    uint32_t ro = base + ATILE_B
                                 + (uint32_t)(kg * 16 + (lane & 15)) * 144
                                 + ntp * 32 + (lane >> 4) * 16;
                    uint32_t vb4[4];
                    ldsm4t(vb4, ro);
                    mma16816(oacc[2*ntp],     ph, vb4);
                    mma16816(oacc[2*ntp + 1], ph, vb4 + 2);
                }
            }
        }
        __syncthreads();
        if (2 * j + 4 < NT) issueKV(2 * j + 4);
        if (2 * j + 5 < NT) issueKV(2 * j + 5);
    }

    // epilogue: write fp16 directly as the proj-GEMM A operand
    const int b = bh >> 4, h = bh & 15;
    #pragma unroll
    for (int r = 0; r < 2; r++) {
        float inv = 1.0f / lrow[r];
        int t = q0 + wid * 16 + g + r * 8;
        size_t rowo = ((size_t)(b * TT + t)) * EMB + h * HS;
        #pragma unroll
        for (int nt = 0; nt < 8; nt++) {
            size_t o = (rowo + nt * 8 + tg * 2) >> 1;
            ((__half2*)g_ahi)[o] =
                __floats2half2_rn(oacc[nt][2*r] * inv, oacc[nt][2*r+1] * inv);
        }
    }
    cudaTriggerProgrammaticLaunchCompletion();
}

// ---------------------------------------------------------------------------
// Host: PDL chain  prep_all -> gemm0 -> attn -> proj
// ---------------------------------------------------------------------------
template<typename K, typename... Args>
static void launch_pdl(K kern, dim3 grid, dim3 block, size_t smem, Args... args)
{
    cudaLaunchConfig_t cfg = {};
    cfg.gridDim = grid;
    cfg.blockDim = block;
    cfg.dynamicSmemBytes = smem;
    cfg.stream = 0;
    cudaLaunchAttribute attrs[1];
    attrs[0].id = cudaLaunchAttributeProgrammaticStreamSerialization;
    attrs[0].val.programmaticStreamSerializationAllowed = 1;
    cfg.attrs = attrs;
    cfg.numAttrs = 1;
    cudaLaunchKernelEx(&cfg, kern, args...);
}

extern "C" void kernel_launch(void* const* d_in, const int* in_sizes, int n_in,
                              void* d_out, int out_size)
{
    const float* x      = (const float*)d_in[0];
    const float* w_qkv  = (const float*)d_in[1];
    const float* w_proj = (const float*)d_in[2];
    const float* b_proj = (const float*)d_in[3];
    float* out = (float*)d_out;

    cudaFuncSetAttribute(attn_mma, cudaFuncAttributeMaxDynamicSharedMemorySize, ATT_SMEM);
    cudaFuncSetAttribute(mma_gemm<0>, cudaFuncAttributeMaxDynamicSharedMemorySize, GEMM_SMEM);
    cudaFuncSetAttribute(mma_gemm<1>, cudaFuncAttributeMaxDynamicSharedMemorySize, GEMM_SMEM);

    __half *xhi, *ahi, *wqhi, *wphi;
    cudaGetSymbolAddress((void**)&xhi,  g_xhi);
    cudaGetSymbolAddress((void**)&ahi,  g_ahi);
    cudaGetSymbolAddress((void**)&wqhi, g_wqhi);
    cudaGetSymbolAddress((void**)&wphi, g_wphi);

    // 1. prep: pure elementwise fp32->fp16 (x + both weights, one launch)
    prep_all<<<8192, 256>>>((const float4*)x,      (__half2*)xhi,
                            (const float4*)w_qkv,  (__half2*)wqhi,
                            (const float4*)w_proj, (__half2*)wphi);

    // 2. QKV GEMM (fp16, BK=64, W native [K][N]) -> q (xQSCALE), k, v
    launch_pdl(mma_gemm<0>, dim3(3 * EMB / 128, NROWS / 128), dim3(256), GEMM_SMEM,
               (const __half*)xhi, (const __half*)wqhi,
               (const float*)nullptr, (float*)nullptr, 3 * EMB);

    // 3. tensor-core causal flash attention (LPT grid, de-phased warps)
    launch_pdl(attn_mma, dim3(BB * HEADS, TT / 128), dim3(256), ATT_SMEM);

    // 4. output projection (fp16, BK=64, W native [K][N]) + bias
    launch_pdl(mma_gemm<1>, dim3(EMB / 128, NROWS / 128), dim3(256), GEMM_SMEM,
               (const __half*)ahi, (const __half*)wphi,
               b_proj, out, EMB);
}